// round 16
// baseline (speedup 1.0000x reference)
#include <cuda_runtime.h>
#include <cstdint>

#define BATCH 4096
#define RNK   64
#define DD    512

// ---------------- static device scratch ------------------------------------
__device__ uint32_t g_phiH[(size_t)BATCH * 1024];   // bf16-hi pairs, [b][cpair]
__device__ uint32_t g_phiL[(size_t)BATCH * 1024];   // bf16-lo pairs (r0 only, c<512)
__device__ uint32_t g_Bh1[32 * 4096 * 8];
__device__ uint32_t g_Bh2[32 * 4096 * 8];
__device__ uint32_t g_Bh3[32 * 2048 * 8];
__device__ float g_R0[BATCH * RNK];
__device__ float g_t1[BATCH * RNK];
__device__ float g_t2[BATCH * RNK];

// ---------------- helpers ---------------------------------------------------
__device__ __forceinline__ uint32_t smem_u32(const void* p) {
    uint32_t a;
    asm("{ .reg .u64 t; cvta.to.shared.u64 t, %1; cvt.u32.u64 %0, t; }"
        : "=r"(a) : "l"(p));
    return a;
}
__device__ __forceinline__ uint32_t pack_bf16(float lo, float hi) {
    uint32_t r;
    asm("cvt.rn.bf16x2.f32 %0, %1, %2;" : "=r"(r) : "f"(hi), "f"(lo));
    return r;
}
__device__ __forceinline__ float bf16lo_f(uint32_t u) { return __uint_as_float(u << 16); }
__device__ __forceinline__ float bf16hi_f(uint32_t u) { return __uint_as_float(u & 0xFFFF0000u); }

// fast 2^t for t <= 0 (clamped), ~1e-8 relative accuracy, pure FMA pipe
__device__ __forceinline__ float fast_exp2(float t) {
    t = fmaxf(t, -126.0f);
    float i = rintf(t);
    float f = t - i;                       // f in [-0.5, 0.5]
    float p = 1.33988744e-3f;
    p = fmaf(p, f, 9.61843736e-3f);
    p = fmaf(p, f, 5.55033251e-2f);
    p = fmaf(p, f, 2.40226479e-1f);
    p = fmaf(p, f, 6.93147203e-1f);
    p = fmaf(p, f, 1.0f);
    return p * __uint_as_float((uint32_t)((int)i + 127) << 23);
}

#define CP_ASYNC16(dst, src) \
    asm volatile("cp.async.cg.shared.global [%0], [%1], 16;" :: "r"(dst), "l"(src) : "memory")
#define CP_COMMIT() asm volatile("cp.async.commit_group;" ::: "memory")
#define CP_WAIT(n)  asm volatile("cp.async.wait_group %0;" :: "n"(n) : "memory")

#define LDSM_X4(r0, r1, r2, r3, addr) \
    asm volatile("ldmatrix.sync.aligned.m8n8.x4.shared.b16 {%0,%1,%2,%3}, [%4];" \
        : "=r"(r0), "=r"(r1), "=r"(r2), "=r"(r3) : "r"(addr))

__device__ __forceinline__ void mma_bf16(float* c, const uint32_t* a, const uint32_t* b) {
    asm volatile(
        "mma.sync.aligned.m16n8k16.row.col.f32.bf16.bf16.f32 "
        "{%0,%1,%2,%3},{%4,%5,%6,%7},{%8,%9},{%0,%1,%2,%3};"
        : "+f"(c[0]), "+f"(c[1]), "+f"(c[2]), "+f"(c[3])
        : "r"(a[0]), "r"(a[1]), "r"(a[2]), "r"(a[3]), "r"(b[0]), "r"(b[1]));
}

// ---------------------------------------------------------------------------
// phi kernel: phi[b][c] = 2^(-max(sq,0)*exp(-2 ls[c])*log2e) -> bf16 hi/lo
// phiL written only for c<512 (only r0 reads it).
// ---------------------------------------------------------------------------
__global__ __launch_bounds__(256) void phi_kernel(const float* __restrict__ X,
                                                  const float* __restrict__ Cn,
                                                  const float* __restrict__ LS)
{
    __shared__ float XsT[32][64];
    __shared__ float CsT[32][64];
    __shared__ float xn[64], cn[64], sg[64];
    const int t  = threadIdx.x;
    const int c0 = blockIdx.x * 64;
    const int b0 = blockIdx.y * 64;

    for (int x = t; x < 64 * 32; x += 256) {
        int r = x >> 5, k = x & 31;
        XsT[k][r] = X[(b0 + r) * 32 + k];
        CsT[k][r] = Cn[(c0 + r) * 32 + k];
    }
    if (t < 64) sg[t] = __expf(-2.0f * LS[c0 + t]) * 1.4426950408889634f;
    __syncthreads();
    if (t < 64) {
        float s = 0.f;
        #pragma unroll
        for (int k = 0; k < 32; k++) { float v = XsT[k][t]; s += v * v; }
        xn[t] = s;
    } else if (t < 128) {
        int c = t - 64; float s = 0.f;
        #pragma unroll
        for (int k = 0; k < 32; k++) { float v = CsT[k][c]; s += v * v; }
        cn[c] = s;
    }
    __syncthreads();

    const int tc = (t & 15) * 4;
    const int tb = (t >> 4) * 4;
    float acc[4][4];
    #pragma unroll
    for (int i = 0; i < 4; i++)
        #pragma unroll
        for (int j = 0; j < 4; j++) acc[i][j] = 0.f;

    #pragma unroll
    for (int k = 0; k < 32; k++) {
        float4 xv = *reinterpret_cast<const float4*>(&XsT[k][tb]);
        float4 cv = *reinterpret_cast<const float4*>(&CsT[k][tc]);
        float xa[4] = {xv.x, xv.y, xv.z, xv.w};
        float ca[4] = {cv.x, cv.y, cv.z, cv.w};
        #pragma unroll
        for (int ci = 0; ci < 4; ci++)
            #pragma unroll
            for (int bi = 0; bi < 4; bi++)
                acc[ci][bi] += ca[ci] * xa[bi];
    }

    #pragma unroll
    for (int bi = 0; bi < 4; bi++) {
        float o[4];
        #pragma unroll
        for (int ci = 0; ci < 4; ci++) {
            float sq = fmaxf(xn[tb + bi] + cn[tc + ci] - 2.0f * acc[ci][bi], 0.0f);
            o[ci] = fast_exp2(-sq * sg[tc + ci]);
        }
        uint32_t h01 = pack_bf16(o[0], o[1]);
        uint32_t h23 = pack_bf16(o[2], o[3]);
        size_t base = (size_t)(b0 + tb + bi) * 1024 + ((c0 + tc) >> 1);
        *reinterpret_cast<uint2*>(&g_phiH[base]) = make_uint2(h01, h23);
        if (c0 < 512) {
            uint32_t l01 = pack_bf16(o[0] - bf16lo_f(h01), o[1] - bf16hi_f(h01));
            uint32_t l23 = pack_bf16(o[2] - bf16lo_f(h23), o[3] - bf16hi_f(h23));
            *reinterpret_cast<uint2*>(&g_phiL[base]) = make_uint2(l01, l23);
        }
    }
}

// ---------------------------------------------------------------------------
// Pack B (merged, j-major): n = j*64 + i.  z=0 G1, z=1 G2, z=2 G3(NOUT=32)
// ---------------------------------------------------------------------------
__global__ __launch_bounds__(256) void packB_all(const float* __restrict__ G1,
                                                 const float* __restrict__ G2,
                                                 const float* __restrict__ G3,
                                                 uint32_t* __restrict__ Bh1,
                                                 uint32_t* __restrict__ Bh2,
                                                 uint32_t* __restrict__ Bh3)
{
    const int z = blockIdx.z;
    const int NOUT = (z == 2) ? 32 : 64;
    const int NB = NOUT * 64;
    const float* G = (z == 0) ? G1 : (z == 1) ? G2 : G3;
    uint32_t* Bh = (z == 0) ? Bh1 : (z == 1) ? Bh2 : Bh3;

    int idx = blockIdx.x * 256 + threadIdx.x;
    if (idx >= NB * 8) return;
    int kt = blockIdx.y;
    int n = idx >> 3, w = idx & 7;
    int j = n >> 6, i = n & 63;          // j-major ordering
    int d = kt * 16 + w * 2;
    float g0 = G[((size_t)i * DD + d) * NOUT + j];
    float g1 = G[((size_t)i * DD + d + 1) * NOUT + j];
    Bh[((size_t)kt * NB + n) * 8 + w] = pack_bf16(g0, g1);
}

// ---------------------------------------------------------------------------
// R0 = Phi0 @ G0 (FFMA, single pass): 128 blocks x (32 b-rows x 64 j), K=512.
// One wave on 148 SMs; no split-K partials, no combine.
// ---------------------------------------------------------------------------
__global__ __launch_bounds__(256) void r0_kernel(const float* __restrict__ G0)
{
    __shared__ float As[32][32];   // [k][b]
    __shared__ float Bs[32][64];   // [k][j]
    const int t  = threadIdx.x;
    const int b0 = blockIdx.x * 32;
    const int tb = (t & 7) * 4;    // 4 b rows
    const int tj = (t >> 3) * 2;   // 2 j cols
    float acc[4][2] = {};

    for (int d0 = 0; d0 < DD; d0 += 32) {
        __syncthreads();
        {   // stage A: 256 threads, each loads 2 pairs (4 k) for one b
            int b = t & 31, pq8 = t >> 5;            // pq8 in 0..7
            size_t base = (size_t)(b0 + b) * 1024 + (d0 >> 1) + pq8 * 2;
            uint2 h2 = *reinterpret_cast<const uint2*>(&g_phiH[base]);
            uint2 l2 = *reinterpret_cast<const uint2*>(&g_phiL[base]);
            As[pq8 * 4 + 0][b] = bf16lo_f(h2.x) + bf16lo_f(l2.x);
            As[pq8 * 4 + 1][b] = bf16hi_f(h2.x) + bf16hi_f(l2.x);
            As[pq8 * 4 + 2][b] = bf16lo_f(h2.y) + bf16lo_f(l2.y);
            As[pq8 * 4 + 3][b] = bf16hi_f(h2.y) + bf16hi_f(l2.y);
        }
        for (int x = t; x < 32 * 64; x += 256) {
            int k = x >> 6, r = x & 63;
            Bs[k][r] = G0[(d0 + k) * RNK + r];
        }
        __syncthreads();
        #pragma unroll
        for (int k = 0; k < 32; k++) {
            float4 a = *reinterpret_cast<const float4*>(&As[k][tb]);
            float2 b = *reinterpret_cast<const float2*>(&Bs[k][tj]);
            float aa[4] = {a.x, a.y, a.z, a.w};
            #pragma unroll
            for (int bi = 0; bi < 4; bi++) {
                acc[bi][0] += aa[bi] * b.x;
                acc[bi][1] += aa[bi] * b.y;
            }
        }
    }
    #pragma unroll
    for (int bi = 0; bi < 4; bi++) {
        *reinterpret_cast<float2*>(&g_R0[(size_t)(b0 + tb + bi) * RNK + tj]) =
            make_float2(acc[bi][0], acc[bi][1]);
    }
}

// ---------------------------------------------------------------------------
// Stage GEMM (mma.sync bf16, j-major B): block 128m x 128n (2 j x 64 i).
// K=64 chunks (4 k16 panels), SWIZZLED panels (4KB, no padding):
//   16B chunk c of row r stored at c ^ ((r>>2)&1)  -> conflict-free LDSM + STS.
// 3 buffers of 32KB (96KB), depth-2 prefetch (CP_WAIT(1)), 8 syncs, 2 CTA/SM.
// ---------------------------------------------------------------------------
template<int NJTOT>
__global__ __launch_bounds__(256, 2) void stage_mma(const float* __restrict__ V,
                                                    const uint32_t* __restrict__ BhG,
                                                    float* __restrict__ OUT,
                                                    int cpair0)
{
    const int NB = NJTOT * 64;
    constexpr uint32_t PAN  = 4096u;          // bytes per k16 panel (128 rows x 32B)
    constexpr uint32_t BUFB = 8u * PAN;       // A0..A3 | B0..B3 = 32768
    extern __shared__ uint32_t sm[];
    const uint32_t smb = smem_u32(sm);

    const int t    = threadIdx.x;
    const int lane = t & 31;
    const int wid  = t >> 5;
    const int wm   = wid >> 2;
    const int wn   = wid & 3;
    const int g    = lane >> 2;
    const int tg   = lane & 3;
    const int b0   = blockIdx.x * 128;
    const int nb0  = blockIdx.y * 128;

    const int row  = t >> 1;
    const int half = t & 1;

    const uint32_t* srcAh = g_phiH + (size_t)(b0 + row) * 1024 + cpair0 + half * 4;
    const uint32_t* srcBh = BhG + ((size_t)(nb0 + row)) * 8 + half * 4;
    // swizzled within-panel byte offset for cp.async dst
    const uint32_t dstOff = (uint32_t)row * 32u +
                            ((uint32_t)(half ^ ((row >> 2) & 1)) << 4);

    // ldmatrix per-lane offsets (bytes, within a panel), swizzled
    const int rr  = lane & 7;
    const int sub = lane >> 3;
    const int ra0 = wm * 64 + rr + ((sub & 1) << 3);
    const int ca  = sub >> 1;
    const uint32_t aoff = (uint32_t)ra0 * 32u +
                          ((uint32_t)((ca ^ ((ra0 >> 2) & 1)) & 1) << 4);
    const int rb0 = wn * 32 + ((sub >> 1) << 3) + rr;
    const int cb  = sub & 1;
    const uint32_t boff = (uint32_t)rb0 * 32u +
                          ((uint32_t)((cb ^ ((rb0 >> 2) & 1)) & 1) << 4);

    float acc[4][4][4];
    #pragma unroll
    for (int a = 0; a < 4; a++)
        #pragma unroll
        for (int b = 0; b < 4; b++)
            #pragma unroll
            for (int c = 0; c < 4; c++) acc[a][b][c] = 0.f;

    // prologue: chunks 0,1 into buffers 0,1
    #pragma unroll
    for (int c = 0; c < 2; c++) {
        const uint32_t bb = smb + (uint32_t)c * BUFB;
        #pragma unroll
        for (int p = 0; p < 4; p++) {
            CP_ASYNC16(bb + p * PAN + dstOff,       srcAh + (4 * c + p) * 8);
            CP_ASYNC16(bb + (4 + p) * PAN + dstOff, srcBh + (size_t)(4 * c + p) * NB * 8);
        }
        CP_COMMIT();
    }

    for (int c = 0; c < 8; c++) {
        if (c < 7) CP_WAIT(1);
        else       CP_WAIT(0);
        __syncthreads();

        // prefetch chunk c+2 into buffer (c+2)%3 (freed by this sync)
        int cn = c + 2;
        if (cn < 8) {
            const uint32_t bb = smb + (uint32_t)(cn % 3) * BUFB;
            #pragma unroll
            for (int p = 0; p < 4; p++) {
                CP_ASYNC16(bb + p * PAN + dstOff,       srcAh + (4 * cn + p) * 8);
                CP_ASYNC16(bb + (4 + p) * PAN + dstOff, srcBh + (size_t)(4 * cn + p) * NB * 8);
            }
            CP_COMMIT();
        }

        const uint32_t base = smb + (uint32_t)(c % 3) * BUFB;
        #pragma unroll
        for (int p = 0; p < 4; p++) {
            uint32_t ah[4][4], bh[4][2];
            const uint32_t pa = base + (uint32_t)p * PAN;
            const uint32_t pb = base + 4u * PAN + (uint32_t)p * PAN;
            #pragma unroll
            for (int mf = 0; mf < 4; mf++)
                LDSM_X4(ah[mf][0], ah[mf][1], ah[mf][2], ah[mf][3], pa + aoff + mf * 512u);
            LDSM_X4(bh[0][0], bh[0][1], bh[1][0], bh[1][1], pb + boff);
            LDSM_X4(bh[2][0], bh[2][1], bh[3][0], bh[3][1], pb + boff + 512u);

            #pragma unroll
            for (int mf = 0; mf < 4; mf++)
                #pragma unroll
                for (int nf = 0; nf < 4; nf++)
                    mma_bf16(acc[mf][nf], ah[mf], bh[nf]);
        }
    }
    __syncthreads();

    // ---- epilogue: full i-fold in-block (identical to R15) -------------
    const int jloc  = wn >> 1;
    const int ihalf = (wn & 1) * 32;
    float s[4][2];
    #pragma unroll
    for (int mf = 0; mf < 4; mf++) { s[mf][0] = 0.f; s[mf][1] = 0.f; }

    #pragma unroll
    for (int mf = 0; mf < 4; mf++) {
        int r = b0 + wm * 64 + mf * 16 + g;
        #pragma unroll
        for (int nf = 0; nf < 4; nf++) {
            int i = ihalf + nf * 8 + tg * 2;
            float2 v0 = *reinterpret_cast<const float2*>(V + (size_t)r * RNK + i);
            float2 v1 = *reinterpret_cast<const float2*>(V + (size_t)(r + 8) * RNK + i);
            s[mf][0] += acc[mf][nf][0] * v0.x + acc[mf][nf][1] * v0.y;
            s[mf][1] += acc[mf][nf][2] * v1.x + acc[mf][nf][3] * v1.y;
        }
    }
    #pragma unroll
    for (int mf = 0; mf < 4; mf++) {
        #pragma unroll
        for (int k = 0; k < 2; k++) {
            s[mf][k] += __shfl_xor_sync(0xffffffffu, s[mf][k], 1);
            s[mf][k] += __shfl_xor_sync(0xffffffffu, s[mf][k], 2);
        }
    }

    float* sred = reinterpret_cast<float*>(sm);   // [128 rows][2 j][2 half]
    if (tg == 0) {
        #pragma unroll
        for (int mf = 0; mf < 4; mf++) {
            int r = wm * 64 + mf * 16 + g;
            sred[r * 4 + jloc * 2 + (wn & 1)]       = s[mf][0];
            sred[(r + 8) * 4 + jloc * 2 + (wn & 1)] = s[mf][1];
        }
    }
    __syncthreads();

    {   // 256 threads: row = t>>1, j = t&1
        int r = t >> 1, j = t & 1;
        float o = sred[r * 4 + j * 2] + sred[r * 4 + j * 2 + 1];
        OUT[(size_t)(b0 + r) * NJTOT + blockIdx.y * 2 + j] = o;
    }
}

// ---------------------------------------------------------------------------
extern "C" void kernel_launch(void* const* d_in, const int* in_sizes, int n_in,
                              void* d_out, int out_size)
{
    const float* X  = (const float*)d_in[0];
    const float* Cn = (const float*)d_in[1];
    const float* LS = (const float*)d_in[2];
    const float* G0 = (const float*)d_in[3];
    const float* G1 = (const float*)d_in[4];
    const float* G2 = (const float*)d_in[5];
    const float* G3 = (const float*)d_in[6];
    float* out = (float*)d_out;

    void *pR0, *pT1, *pT2, *pBh1, *pBh2, *pBh3;
    cudaGetSymbolAddress(&pR0, g_R0);
    cudaGetSymbolAddress(&pT1, g_t1);
    cudaGetSymbolAddress(&pT2, g_t2);
    cudaGetSymbolAddress(&pBh1, g_Bh1);
    cudaGetSymbolAddress(&pBh2, g_Bh2);
    cudaGetSymbolAddress(&pBh3, g_Bh3);

    const int smemStage = 3 * 32768;   // 98304 B (3 bufs x 32KB, swizzled)
    static int s_init = 0;
    if (!s_init) {
        cudaFuncSetAttribute((const void*)stage_mma<64>,
                             cudaFuncAttributeMaxDynamicSharedMemorySize, smemStage);
        cudaFuncSetAttribute((const void*)stage_mma<32>,
                             cudaFuncAttributeMaxDynamicSharedMemorySize, smemStage);
        s_init = 1;
    }

    phi_kernel<<<dim3(2048 / 64, BATCH / 64), 256>>>(X, Cn, LS);
    packB_all<<<dim3(128, 32, 3), 256>>>(G1, G2, G3,
        (uint32_t*)pBh1, (uint32_t*)pBh2, (uint32_t*)pBh3);

    r0_kernel<<<BATCH / 32, 256>>>(G0);

    stage_mma<64><<<dim3(BATCH / 128, 32), 256, smemStage>>>(
        (const float*)pR0, (const uint32_t*)pBh1, (float*)pT1, 256);

    stage_mma<64><<<dim3(BATCH / 128, 32), 256, smemStage>>>(
        (const float*)pT1, (const uint32_t*)pBh2, (float*)pT2, 512);

    stage_mma<32><<<dim3(BATCH / 128, 16), 256, smemStage>>>(
        (const float*)pT2, (const uint32_t*)pBh3, out, 768);
}

// round 17
// speedup vs baseline: 1.0753x; 1.0753x over previous
#include <cuda_runtime.h>
#include <cstdint>

#define BATCH 4096
#define RNK   64
#define DD    512

// ---------------- static device scratch ------------------------------------
__device__ uint32_t g_phiH[(size_t)BATCH * 1024];   // bf16-hi pairs, [b][cpair]
__device__ uint32_t g_phiL[(size_t)BATCH * 1024];   // bf16-lo pairs (r0 only, c<512)
__device__ uint32_t g_Bh1[32 * 4096 * 8];
__device__ uint32_t g_Bh2[32 * 4096 * 8];
__device__ uint32_t g_Bh3[32 * 2048 * 8];
__device__ float g_R0[BATCH * RNK];
__device__ float g_t1[BATCH * RNK];
__device__ float g_t2[BATCH * RNK];
__device__ float g_part[(size_t)4 * BATCH * RNK];   // r0 split-K partials
__device__ int   g_cnt1[32];                        // stage1 completion per bx
__device__ int   g_cnt2[32];                        // stage2 completion per bx

// ---------------- helpers ---------------------------------------------------
__device__ __forceinline__ uint32_t smem_u32(const void* p) {
    uint32_t a;
    asm("{ .reg .u64 t; cvta.to.shared.u64 t, %1; cvt.u32.u64 %0, t; }"
        : "=r"(a) : "l"(p));
    return a;
}
__device__ __forceinline__ uint32_t pack_bf16(float lo, float hi) {
    uint32_t r;
    asm("cvt.rn.bf16x2.f32 %0, %1, %2;" : "=r"(r) : "f"(hi), "f"(lo));
    return r;
}
__device__ __forceinline__ float bf16lo_f(uint32_t u) { return __uint_as_float(u << 16); }
__device__ __forceinline__ float bf16hi_f(uint32_t u) { return __uint_as_float(u & 0xFFFF0000u); }

// fast 2^t for t <= 0 (clamped), ~1e-8 relative accuracy, pure FMA pipe
__device__ __forceinline__ float fast_exp2(float t) {
    t = fmaxf(t, -126.0f);
    float i = rintf(t);
    float f = t - i;                       // f in [-0.5, 0.5]
    float p = 1.33988744e-3f;
    p = fmaf(p, f, 9.61843736e-3f);
    p = fmaf(p, f, 5.55033251e-2f);
    p = fmaf(p, f, 2.40226479e-1f);
    p = fmaf(p, f, 6.93147203e-1f);
    p = fmaf(p, f, 1.0f);
    return p * __uint_as_float((uint32_t)((int)i + 127) << 23);
}

#define CP_ASYNC16(dst, src) \
    asm volatile("cp.async.cg.shared.global [%0], [%1], 16;" :: "r"(dst), "l"(src) : "memory")
#define CP_COMMIT() asm volatile("cp.async.commit_group;" ::: "memory")
#define CP_WAIT(n)  asm volatile("cp.async.wait_group %0;" :: "n"(n) : "memory")

#define LDSM_X4(r0, r1, r2, r3, addr) \
    asm volatile("ldmatrix.sync.aligned.m8n8.x4.shared.b16 {%0,%1,%2,%3}, [%4];" \
        : "=r"(r0), "=r"(r1), "=r"(r2), "=r"(r3) : "r"(addr))

__device__ __forceinline__ void mma_bf16(float* c, const uint32_t* a, const uint32_t* b) {
    asm volatile(
        "mma.sync.aligned.m16n8k16.row.col.f32.bf16.bf16.f32 "
        "{%0,%1,%2,%3},{%4,%5,%6,%7},{%8,%9},{%0,%1,%2,%3};"
        : "+f"(c[0]), "+f"(c[1]), "+f"(c[2]), "+f"(c[3])
        : "r"(a[0]), "r"(a[1]), "r"(a[2]), "r"(a[3]), "r"(b[0]), "r"(b[1]));
}

// ---------------------------------------------------------------------------
// phi kernel: phi[b][c] = 2^(-max(sq,0)*exp(-2 ls[c])*log2e) -> bf16 hi/lo
// phiL written only for c<512 (only r0 reads it).
// ---------------------------------------------------------------------------
__global__ __launch_bounds__(256) void phi_kernel(const float* __restrict__ X,
                                                  const float* __restrict__ Cn,
                                                  const float* __restrict__ LS)
{
    __shared__ float XsT[32][64];
    __shared__ float CsT[32][64];
    __shared__ float xn[64], cn[64], sg[64];
    const int t  = threadIdx.x;
    const int c0 = blockIdx.x * 64;
    const int b0 = blockIdx.y * 64;

    for (int x = t; x < 64 * 32; x += 256) {
        int r = x >> 5, k = x & 31;
        XsT[k][r] = X[(b0 + r) * 32 + k];
        CsT[k][r] = Cn[(c0 + r) * 32 + k];
    }
    if (t < 64) sg[t] = __expf(-2.0f * LS[c0 + t]) * 1.4426950408889634f;
    __syncthreads();
    if (t < 64) {
        float s = 0.f;
        #pragma unroll
        for (int k = 0; k < 32; k++) { float v = XsT[k][t]; s += v * v; }
        xn[t] = s;
    } else if (t < 128) {
        int c = t - 64; float s = 0.f;
        #pragma unroll
        for (int k = 0; k < 32; k++) { float v = CsT[k][c]; s += v * v; }
        cn[c] = s;
    }
    __syncthreads();

    const int tc = (t & 15) * 4;
    const int tb = (t >> 4) * 4;
    float acc[4][4];
    #pragma unroll
    for (int i = 0; i < 4; i++)
        #pragma unroll
        for (int j = 0; j < 4; j++) acc[i][j] = 0.f;

    #pragma unroll
    for (int k = 0; k < 32; k++) {
        float4 xv = *reinterpret_cast<const float4*>(&XsT[k][tb]);
        float4 cv = *reinterpret_cast<const float4*>(&CsT[k][tc]);
        float xa[4] = {xv.x, xv.y, xv.z, xv.w};
        float ca[4] = {cv.x, cv.y, cv.z, cv.w};
        #pragma unroll
        for (int ci = 0; ci < 4; ci++)
            #pragma unroll
            for (int bi = 0; bi < 4; bi++)
                acc[ci][bi] += ca[ci] * xa[bi];
    }

    #pragma unroll
    for (int bi = 0; bi < 4; bi++) {
        float o[4];
        #pragma unroll
        for (int ci = 0; ci < 4; ci++) {
            float sq = fmaxf(xn[tb + bi] + cn[tc + ci] - 2.0f * acc[ci][bi], 0.0f);
            o[ci] = fast_exp2(-sq * sg[tc + ci]);
        }
        uint32_t h01 = pack_bf16(o[0], o[1]);
        uint32_t h23 = pack_bf16(o[2], o[3]);
        size_t base = (size_t)(b0 + tb + bi) * 1024 + ((c0 + tc) >> 1);
        *reinterpret_cast<uint2*>(&g_phiH[base]) = make_uint2(h01, h23);
        if (c0 < 512) {
            uint32_t l01 = pack_bf16(o[0] - bf16lo_f(h01), o[1] - bf16hi_f(h01));
            uint32_t l23 = pack_bf16(o[2] - bf16lo_f(h23), o[3] - bf16hi_f(h23));
            *reinterpret_cast<uint2*>(&g_phiL[base]) = make_uint2(l01, l23);
        }
    }
}

// ---------------------------------------------------------------------------
// Pack B (merged, j-major): n = j*64 + i.  z=0 G1, z=1 G2, z=2 G3(NOUT=32)
// ---------------------------------------------------------------------------
__global__ __launch_bounds__(256) void packB_all(const float* __restrict__ G1,
                                                 const float* __restrict__ G2,
                                                 const float* __restrict__ G3,
                                                 uint32_t* __restrict__ Bh1,
                                                 uint32_t* __restrict__ Bh2,
                                                 uint32_t* __restrict__ Bh3)
{
    const int z = blockIdx.z;
    const int NOUT = (z == 2) ? 32 : 64;
    const int NB = NOUT * 64;
    const float* G = (z == 0) ? G1 : (z == 1) ? G2 : G3;
    uint32_t* Bh = (z == 0) ? Bh1 : (z == 1) ? Bh2 : Bh3;

    int idx = blockIdx.x * 256 + threadIdx.x;
    if (idx >= NB * 8) return;
    int kt = blockIdx.y;
    int n = idx >> 3, w = idx & 7;
    int j = n >> 6, i = n & 63;          // j-major ordering
    int d = kt * 16 + w * 2;
    float g0 = G[((size_t)i * DD + d) * NOUT + j];
    float g1 = G[((size_t)i * DD + d + 1) * NOUT + j];
    Bh[((size_t)kt * NB + n) * 8 + w] = pack_bf16(g0, g1);
}

// ---------------------------------------------------------------------------
// R0 = Phi0 @ G0 (FFMA, split-K x4 -> g_part)
// ---------------------------------------------------------------------------
__global__ __launch_bounds__(256) void r0_kernel(const float* __restrict__ G0)
{
    __shared__ float As[32][64];
    __shared__ float Bs[32][64];
    const int t  = threadIdx.x;
    const int b0 = blockIdx.x * 64;
    const int dbase = blockIdx.y * 128;
    const int tb = (t & 15) * 4;
    const int tj = (t >> 4) * 4;
    float acc[4][4] = {};

    for (int d0 = dbase; d0 < dbase + 128; d0 += 32) {
        __syncthreads();
        {
            int b = t >> 2, pq = t & 3;
            size_t base = (size_t)(b0 + b) * 1024 + (d0 >> 1) + pq * 4;
            uint4 h4 = *reinterpret_cast<const uint4*>(&g_phiH[base]);
            uint4 l4 = *reinterpret_cast<const uint4*>(&g_phiL[base]);
            uint32_t hh[4] = {h4.x, h4.y, h4.z, h4.w};
            uint32_t ll[4] = {l4.x, l4.y, l4.z, l4.w};
            #pragma unroll
            for (int q = 0; q < 4; q++) {
                As[pq * 8 + q * 2 + 0][b] = bf16lo_f(hh[q]) + bf16lo_f(ll[q]);
                As[pq * 8 + q * 2 + 1][b] = bf16hi_f(hh[q]) + bf16hi_f(ll[q]);
            }
        }
        for (int x = t; x < 32 * 64; x += 256) {
            int k = x >> 6, r = x & 63;
            Bs[k][r] = G0[(d0 + k) * RNK + r];
        }
        __syncthreads();
        #pragma unroll
        for (int k = 0; k < 32; k++) {
            float4 a = *reinterpret_cast<const float4*>(&As[k][tb]);
            float4 b = *reinterpret_cast<const float4*>(&Bs[k][tj]);
            float aa[4] = {a.x, a.y, a.z, a.w};
            float bb[4] = {b.x, b.y, b.z, b.w};
            #pragma unroll
            for (int bi = 0; bi < 4; bi++)
                #pragma unroll
                for (int ji = 0; ji < 4; ji++)
                    acc[bi][ji] += aa[bi] * bb[ji];
        }
    }
    float* outp = g_part + (size_t)blockIdx.y * (BATCH * RNK);
    #pragma unroll
    for (int bi = 0; bi < 4; bi++)
        #pragma unroll
        for (int ji = 0; ji < 4; ji++)
            outp[(b0 + tb + bi) * RNK + tj + ji] = acc[bi][ji];
}

// ---------------------------------------------------------------------------
// combine: R0 = sum over 4 r0 split-K planes, float4; also zeroes stage counters.
// ---------------------------------------------------------------------------
__global__ void combine_kernel(float* __restrict__ dst)
{
    if (blockIdx.x == 0 && threadIdx.x < 32) {
        g_cnt1[threadIdx.x] = 0;
        g_cnt2[threadIdx.x] = 0;
    }
    int n4 = BATCH * RNK / 4;
    int x = blockIdx.x * blockDim.x + threadIdx.x;
    if (x < n4) {
        const float4* p = reinterpret_cast<const float4*>(g_part);
        float4 s = p[x];
        #pragma unroll
        for (int g = 1; g < 4; g++) {
            float4 v = p[(size_t)g * n4 + x];
            s.x += v.x; s.y += v.y; s.z += v.z; s.w += v.w;
        }
        reinterpret_cast<float4*>(dst)[x] = s;
    }
}

// ---------------------------------------------------------------------------
// FUSED stage GEMMs (mma.sync bf16, j-major B), one flat grid:
//   blocks [0,1024)    : stage 1  (V=R0,  B=Bh1, OUT=t1,  cpair0=256, NJ=64)
//   blocks [1024,2048) : stage 2  (V=t1,  B=Bh2, OUT=t2,  cpair0=512, NJ=64)
//   blocks [2048,2560) : stage 3  (V=t2,  B=Bh3, OUT=out, cpair0=768, NJ=32)
// Mainloop independent of V; consumers spin on per-bx counters only before
// the epilogue V-fold. Block 128m x 128n, K=64 chunks, swizzled 4KB panels,
// 3 buffers (96KB), depth-2 prefetch, 2 CTAs/SM.
// ---------------------------------------------------------------------------
__global__ __launch_bounds__(256, 2) void stages_fused(const float* __restrict__ R0v,
                                                       const uint32_t* __restrict__ B1,
                                                       const uint32_t* __restrict__ B2,
                                                       const uint32_t* __restrict__ B3,
                                                       float* __restrict__ FOUT)
{
    constexpr uint32_t PAN  = 4096u;
    constexpr uint32_t BUFB = 8u * PAN;       // 32768
    extern __shared__ uint32_t sm[];
    const uint32_t smb = smem_u32(sm);

    const int xblk = blockIdx.x;
    int s, r;
    if (xblk < 1024)      { s = 0; r = xblk; }
    else if (xblk < 2048) { s = 1; r = xblk - 1024; }
    else                  { s = 2; r = xblk - 2048; }
    const int bx = r & 31;
    const int by = r >> 5;

    const float*    V   = (s == 0) ? R0v : (s == 1) ? g_t1 : g_t2;
    const uint32_t* BhG = (s == 0) ? B1  : (s == 1) ? B2  : B3;
    float*          OUT = (s == 0) ? g_t1 : (s == 1) ? g_t2 : FOUT;
    const int cpair0 = 256 + s * 256;
    const int NJ     = (s == 2) ? 32 : 64;
    const int NB     = NJ * 64;

    const int t    = threadIdx.x;
    const int lane = t & 31;
    const int wid  = t >> 5;
    const int wm   = wid >> 2;
    const int wn   = wid & 3;
    const int g    = lane >> 2;
    const int tg   = lane & 3;
    const int b0   = bx * 128;
    const int nb0  = by * 128;

    const int row  = t >> 1;
    const int half = t & 1;

    const uint32_t* srcAh = g_phiH + (size_t)(b0 + row) * 1024 + cpair0 + half * 4;
    const uint32_t* srcBh = BhG + ((size_t)(nb0 + row)) * 8 + half * 4;
    const uint32_t dstOff = (uint32_t)row * 32u +
                            ((uint32_t)(half ^ ((row >> 2) & 1)) << 4);

    const int rr  = lane & 7;
    const int sub = lane >> 3;
    const int ra0 = wm * 64 + rr + ((sub & 1) << 3);
    const int ca  = sub >> 1;
    const uint32_t aoff = (uint32_t)ra0 * 32u +
                          ((uint32_t)((ca ^ ((ra0 >> 2) & 1)) & 1) << 4);
    const int rb0 = wn * 32 + ((sub >> 1) << 3) + rr;
    const int cb  = sub & 1;
    const uint32_t boff = (uint32_t)rb0 * 32u +
                          ((uint32_t)((cb ^ ((rb0 >> 2) & 1)) & 1) << 4);

    float acc[4][4][4];
    #pragma unroll
    for (int a = 0; a < 4; a++)
        #pragma unroll
        for (int b = 0; b < 4; b++)
            #pragma unroll
            for (int c = 0; c < 4; c++) acc[a][b][c] = 0.f;

    // prologue: chunks 0,1 into buffers 0,1
    #pragma unroll
    for (int c = 0; c < 2; c++) {
        const uint32_t bb = smb + (uint32_t)c * BUFB;
        #pragma unroll
        for (int p = 0; p < 4; p++) {
            CP_ASYNC16(bb + p * PAN + dstOff,       srcAh + (4 * c + p) * 8);
            CP_ASYNC16(bb + (4 + p) * PAN + dstOff, srcBh + (size_t)(4 * c + p) * NB * 8);
        }
        CP_COMMIT();
    }

    for (int c = 0; c < 8; c++) {
        if (c < 7) CP_WAIT(1);
        else       CP_WAIT(0);
        __syncthreads();

        int cn = c + 2;
        if (cn < 8) {
            const uint32_t bb = smb + (uint32_t)(cn % 3) * BUFB;
            #pragma unroll
            for (int p = 0; p < 4; p++) {
                CP_ASYNC16(bb + p * PAN + dstOff,       srcAh + (4 * cn + p) * 8);
                CP_ASYNC16(bb + (4 + p) * PAN + dstOff, srcBh + (size_t)(4 * cn + p) * NB * 8);
            }
            CP_COMMIT();
        }

        const uint32_t base = smb + (uint32_t)(c % 3) * BUFB;
        #pragma unroll
        for (int p = 0; p < 4; p++) {
            uint32_t ah[4][4], bh[4][2];
            const uint32_t pa = base + (uint32_t)p * PAN;
            const uint32_t pb = base + 4u * PAN + (uint32_t)p * PAN;
            #pragma unroll
            for (int mf = 0; mf < 4; mf++)
                LDSM_X4(ah[mf][0], ah[mf][1], ah[mf][2], ah[mf][3], pa + aoff + mf * 512u);
            LDSM_X4(bh[0][0], bh[0][1], bh[1][0], bh[1][1], pb + boff);
            LDSM_X4(bh[2][0], bh[2][1], bh[3][0], bh[3][1], pb + boff + 512u);

            #pragma unroll
            for (int mf = 0; mf < 4; mf++)
                #pragma unroll
                for (int nf = 0; nf < 4; nf++)
                    mma_bf16(acc[mf][nf], ah[mf], bh[nf]);
        }
    }
    __syncthreads();

    // ---- wait for producer stage's rows (consumers only) ---------------
    if (s > 0) {
        if (t == 0) {
            volatile int* cp = (s == 1) ? &g_cnt1[bx] : &g_cnt2[bx];
            while (*cp < 32) __nanosleep(64);
            __threadfence();
        }
        __syncthreads();
    }

    // ---- epilogue: full i-fold in-block --------------------------------
    const int jloc  = wn >> 1;
    const int ihalf = (wn & 1) * 32;
    float sv[4][2];
    #pragma unroll
    for (int mf = 0; mf < 4; mf++) { sv[mf][0] = 0.f; sv[mf][1] = 0.f; }

    #pragma unroll
    for (int mf = 0; mf < 4; mf++) {
        int rr2 = b0 + wm * 64 + mf * 16 + g;
        #pragma unroll
        for (int nf = 0; nf < 4; nf++) {
            int i = ihalf + nf * 8 + tg * 2;
            float2 v0 = *reinterpret_cast<const float2*>(V + (size_t)rr2 * RNK + i);
            float2 v1 = *reinterpret_cast<const float2*>(V + (size_t)(rr2 + 8) * RNK + i);
            sv[mf][0] += acc[mf][nf][0] * v0.x + acc[mf][nf][1] * v0.y;
            sv[mf][1] += acc[mf][nf][2] * v1.x + acc[mf][nf][3] * v1.y;
        }
    }
    #pragma unroll
    for (int mf = 0; mf < 4; mf++) {
        #pragma unroll
        for (int k = 0; k < 2; k++) {
            sv[mf][k] += __shfl_xor_sync(0xffffffffu, sv[mf][k], 1);
            sv[mf][k] += __shfl_xor_sync(0xffffffffu, sv[mf][k], 2);
        }
    }

    float* sred = reinterpret_cast<float*>(sm);
    if (tg == 0) {
        #pragma unroll
        for (int mf = 0; mf < 4; mf++) {
            int rr2 = wm * 64 + mf * 16 + g;
            sred[rr2 * 4 + jloc * 2 + (wn & 1)]       = sv[mf][0];
            sred[(rr2 + 8) * 4 + jloc * 2 + (wn & 1)] = sv[mf][1];
        }
    }
    __syncthreads();

    {   // 256 threads: row = t>>1, j = t&1
        int rr2 = t >> 1, j = t & 1;
        float o = sred[rr2 * 4 + j * 2] + sred[rr2 * 4 + j * 2 + 1];
        OUT[(size_t)(b0 + rr2) * NJ + by * 2 + j] = o;
    }

    // ---- signal completion (producer stages only) ----------------------
    if (s < 2) {
        __threadfence();
        __syncthreads();
        if (t == 0) {
            if (s == 0) atomicAdd(&g_cnt1[bx], 1);
            else        atomicAdd(&g_cnt2[bx], 1);
        }
    }
}

// ---------------------------------------------------------------------------
extern "C" void kernel_launch(void* const* d_in, const int* in_sizes, int n_in,
                              void* d_out, int out_size)
{
    const float* X  = (const float*)d_in[0];
    const float* Cn = (const float*)d_in[1];
    const float* LS = (const float*)d_in[2];
    const float* G0 = (const float*)d_in[3];
    const float* G1 = (const float*)d_in[4];
    const float* G2 = (const float*)d_in[5];
    const float* G3 = (const float*)d_in[6];
    float* out = (float*)d_out;

    void *pR0, *pBh1, *pBh2, *pBh3;
    cudaGetSymbolAddress(&pR0, g_R0);
    cudaGetSymbolAddress(&pBh1, g_Bh1);
    cudaGetSymbolAddress(&pBh2, g_Bh2);
    cudaGetSymbolAddress(&pBh3, g_Bh3);

    const int smemStage = 3 * 32768;   // 98304 B
    static int s_init = 0;
    if (!s_init) {
        cudaFuncSetAttribute((const void*)stages_fused,
                             cudaFuncAttributeMaxDynamicSharedMemorySize, smemStage);
        s_init = 1;
    }

    phi_kernel<<<dim3(2048 / 64, BATCH / 64), 256>>>(X, Cn, LS);
    packB_all<<<dim3(128, 32, 3), 256>>>(G1, G2, G3,
        (uint32_t*)pBh1, (uint32_t*)pBh2, (uint32_t*)pBh3);

    r0_kernel<<<dim3(BATCH / 64, 4), 256>>>(G0);
    combine_kernel<<<(BATCH * RNK / 4 + 255) / 256, 256>>>((float*)pR0);

    stages_fused<<<2560, 256, smemStage>>>(
        (const float*)pR0, (const uint32_t*)pBh1, (const uint32_t*)pBh2,
        (const uint32_t*)pBh3, out);
}